// round 2
// baseline (speedup 1.0000x reference)
#include <cuda_runtime.h>
#include <cstdint>

// conv_layer_65000035058096
// out[b,v,o] = sum_{j=0..6} sum_{k=0..63} x[b, nb[v*7+j], k] * W[o, j*64+k] + bias[o]
//
// GEMM view: M = B*V, K = 448, N = 64 with gathered A.
// Strategy: 128-vertex x 64-output tiles, 14 K-chunks of 32,
// fp32 math via packed fma.rn.f32x2 (FFMA2) to hit 128 FMA/cyc/SM.
//
// NOTE: neigh_orders is int32 on device (JAX x64 disabled downgrades the
// requested int64 to int32).

#define V_TOT   163842
#define NBATCH  2
#define TILE_V  128
#define A_STRIDE 33    // 32 + 1 pad: (33*tv) % 32 == tv -> conflict-free a-loads
#define OS_STRIDE 65   // epilogue staging pad

// W transposed to k-major: g_Wt[k*64 + o] = W[o*448 + k]
__device__ float g_Wt[448 * 64];

__global__ void transpose_W_kernel(const float* __restrict__ W) {
    int idx = blockIdx.x * blockDim.x + threadIdx.x;
    if (idx < 448 * 64) {
        int k = idx >> 6;
        int o = idx & 63;
        g_Wt[idx] = W[o * 448 + k];
    }
}

__global__ __launch_bounds__(256, 3)
void sconv_kernel(const float* __restrict__ x,
                  const int* __restrict__ nb,
                  const float* __restrict__ bias,
                  float* __restrict__ out) {
    // union: staging (As 128*33 + Ws 32*64 = 6272 floats) vs epilogue (128*65 = 8320)
    __shared__ float smem[TILE_V * OS_STRIDE];   // 33,280 B static
    float* As = smem;                            // [128][33]
    float* Ws = smem + TILE_V * A_STRIDE;        // [32][64], k-major

    const int t   = threadIdx.x;
    const int tv  = t & 31;          // lane -> vertex group
    const int wo  = (t >> 5) << 3;   // warp -> 8-output base (all lanes share)
    const int batch = blockIdx.y;
    const int v0    = blockIdx.x * TILE_V;

    // 4 vertices x 4 f32x2 output-pairs per thread
    unsigned long long acc[4][4];
#pragma unroll
    for (int i = 0; i < 4; ++i)
#pragma unroll
        for (int p = 0; p < 4; ++p) acc[i][p] = 0ull;

    const int f   = t & 7;   // float4 slot within the 32-float half-row
    const int vl0 = t >> 3;  // 0..31

    for (int c = 0; c < 14; ++c) {
        const int j     = c >> 1;         // neighbor index 0..6
        const int kbase = (c & 1) << 5;   // 0 or 32 within the neighbor row

        // --- stage W chunk (coalesced read from k-major g_Wt, conflict-free write)
        {
            const int wgbase = (j * 64 + kbase) * 64;
#pragma unroll
            for (int r = 0; r < 8; ++r)
                Ws[t + r * 256] = g_Wt[wgbase + t + r * 256];
        }

        // --- stage A chunk: gather 128 half-rows of 32 floats via float4
#pragma unroll
        for (int i = 0; i < 4; ++i) {
            const int vl = vl0 + (i << 5);
            const int vg = v0 + vl;
            if (vg < V_TOT) {
                const int r = nb[vg * 7 + j];
                const float4 d = *reinterpret_cast<const float4*>(
                    x + (((long long)batch * V_TOT + r) << 6) + kbase + (f << 2));
                float* dst = As + vl * A_STRIDE + (f << 2);
                dst[0] = d.x; dst[1] = d.y; dst[2] = d.z; dst[3] = d.w;
            }
        }
        __syncthreads();

        // --- compute: per kk: 4 a-LDS (conflict-free) + 4 w-LDS.64 (broadcast)
        //              + 4 packs + 16 FFMA2  -> FFMA2-pipe bound
#pragma unroll 8
        for (int kk = 0; kk < 32; ++kk) {
            unsigned long long wv[4];
            const unsigned long long* wrow =
                reinterpret_cast<const unsigned long long*>(Ws + (kk << 6) + wo);
#pragma unroll
            for (int p = 0; p < 4; ++p) wv[p] = wrow[p];
#pragma unroll
            for (int i = 0; i < 4; ++i) {
                float a = As[(tv + (i << 5)) * A_STRIDE + kk];
                unsigned long long a2;
                asm("mov.b64 %0, {%1, %1};" : "=l"(a2) : "f"(a));
#pragma unroll
                for (int p = 0; p < 4; ++p)
                    asm("fma.rn.f32x2 %0, %1, %2, %0;"
                        : "+l"(acc[i][p]) : "l"(a2), "l"(wv[p]));
            }
        }
        __syncthreads();
    }

    // --- epilogue: stage results in smem (conflict-free), then coalesced store
#pragma unroll
    for (int i = 0; i < 4; ++i) {
        float* orow = smem + (tv + (i << 5)) * OS_STRIDE + wo;
#pragma unroll
        for (int p = 0; p < 4; ++p) {
            float lo, hi;
            asm("mov.b64 {%0, %1}, %2;" : "=f"(lo), "=f"(hi) : "l"(acc[i][p]));
            orow[2 * p]     = lo;
            orow[2 * p + 1] = hi;
        }
    }
    __syncthreads();

#pragma unroll
    for (int r = 0; r < 32; ++r) {
        const int idx = t + (r << 8);
        const int vl  = idx >> 6;
        const int o   = idx & 63;
        const int vg  = v0 + vl;
        if (vg < V_TOT)
            out[(((long long)batch * V_TOT + vg) << 6) + o] =
                smem[vl * OS_STRIDE + o] + bias[o];
    }
}

extern "C" void kernel_launch(void* const* d_in, const int* in_sizes, int n_in,
                              void* d_out, int out_size) {
    const float* x   = (const float*)d_in[0];   // (2, V, 64) f32
    const int*   nb  = (const int*)d_in[1];     // (V*7,) i32 (JAX x64 off)
    const float* W   = (const float*)d_in[2];   // (64, 448) f32
    const float* b   = (const float*)d_in[3];   // (64,) f32
    float*       out = (float*)d_out;           // (2, V, 64) f32

    transpose_W_kernel<<<(448 * 64 + 255) / 256, 256>>>(W);

    dim3 grid((V_TOT + TILE_V - 1) / TILE_V, NBATCH);
    sconv_kernel<<<grid, 256>>>(x, nb, b, out);
}